// round 11
// baseline (speedup 1.0000x reference)
#include <cuda_runtime.h>
#include <math.h>

#define NN 2048
#define MM 32
#define NMOM 8                 // moments M_0..M_7 (degree-7 erf series)
#define GAA 64                 // kA grid
#define TBA 512                // kA threads (16 warps), 2 elements/thread
#define NWA 16
#define GBB 128                // kB grid
#define TBB 512                // kB threads (16 warps), 1 element/thread
#define NWBB 16

// ---- scratch (no device allocations allowed) ----
__device__ float g_pmom[GAA][NMOM][MM]; // per-block raw weighted moments
__device__ float g_pmax[GAA][MM];       // per-block per-column max(diff)
__device__ float g_bco[NMOM + 1][MM];   // b_0..b_7, row NMOM = W   (built by kC)
__device__ float g_f[MM];               // per-column normalization factor
__device__ float g_part[GBB];           // kB per-block partial loss

// A[m][p] = C[(m+p-1)/2] * binom(m+p, m) * (-1)^p for (m+p) odd <= 7, else 0.
// 0.5*erf(d) ~ C0 d + C1 d^3 + C2 d^5 + C3 d^7  (|d| <= 0.3536, trunc ~5e-7 rel)
__device__ __constant__ float d_A[NMOM][NMOM] = {
  {0.f,-0.5641895835477563f,0.f, 0.18806319451591878f,0.f,-0.05641895835477563f,0.f, 0.013433085322565627f},
  {0.5641895835477563f,0.f,-0.5641895835477563f,0.f, 0.28209479177387815f,0.f,-0.09403159725795939f,0.f},
  {0.f, 0.5641895835477563f,0.f,-0.5641895835477563f,0.f, 0.28209479177387817f,0.f,0.f},
  {-0.18806319451591878f,0.f, 0.5641895835477563f,0.f,-0.47015798628979696f,0.f,0.f,0.f},
  {0.f,-0.28209479177387815f,0.f, 0.47015798628979696f,0.f,0.f,0.f,0.f},
  {0.05641895835477563f,0.f,-0.28209479177387817f,0.f,0.f,0.f,0.f,0.f},
  {0.f, 0.09403159725795939f,0.f,0.f,0.f,0.f,0.f,0.f},
  {-0.013433085322565627f,0.f,0.f,0.f,0.f,0.f,0.f,0.f}
};

// ---------------------------------------------------------------------------
// kA: raw weighted moments + per-column max partials. 2 elements per thread.
// ---------------------------------------------------------------------------
__global__ void __launch_bounds__(TBA, 1) kA(const float* __restrict__ risk,
                                             const float* __restrict__ expr,
                                             const float* __restrict__ tr) {
    const int tid  = threadIdx.x;
    const int warp = tid >> 5, lane = tid & 31;

    __shared__ float smom[NWA][NMOM][MM];   // 16 KB
    __shared__ float smax[NWA][MM];         // 2 KB

    const int i0 = blockIdx.x * (2 * TBA) + tid;   // element 0
    const int i1 = i0 + TBA;                       // element 1 (same lane/column)

    const float d0 = expr[i0] - tr[i0];
    const float d1 = expr[i1] - tr[i1];
    const float T0 = __expf(d0),       T1 = __expf(d1);
    float       p0 = __expf(risk[i0]), p1 = __expf(risk[i1]);

    smax[warp][lane] = fmaxf(d0, d1);
    smom[warp][0][lane] = p0 + p1;
#pragma unroll
    for (int q = 1; q < NMOM; ++q) {
        p0 *= T0; p1 *= T1;
        smom[warp][q][lane] = p0 + p1;
    }
    __syncthreads();

    if (tid < 32) {                        // column max over 16 warps
        float v = smax[0][tid];
#pragma unroll
        for (int i = 1; i < NWA; ++i) v = fmaxf(v, smax[i][tid]);
        g_pmax[blockIdx.x][tid] = v;
    }
    if (tid < NMOM * MM) {                 // moment sums over 16 warps (4-acc)
        const int q = tid >> 5, kk = tid & 31;
        float s0 = 0.f, s1 = 0.f, s2 = 0.f, s3 = 0.f;
#pragma unroll
        for (int i = 0; i < NWA; i += 4) {
            s0 += smom[i + 0][q][kk];
            s1 += smom[i + 1][q][kk];
            s2 += smom[i + 2][q][kk];
            s3 += smom[i + 3][q][kk];
        }
        g_pmom[blockIdx.x][q][kk] = (s0 + s1) + (s2 + s3);
    }
}

// ---------------------------------------------------------------------------
// kC: single block — reduce partials -> f, normalized moments, coefficients.
// ---------------------------------------------------------------------------
__global__ void __launch_bounds__(512) kC(const float* __restrict__ sigma) {
    const int tid  = threadIdx.x;
    const int lane = tid & 31;

    __shared__ float sred[2][NMOM][MM];
    __shared__ float smax2[8][MM];
    __shared__ float sM[NMOM][MM];
    __shared__ float sf[MM];

    {
        const int j = tid >> 8;                    // 0..1
        const int o = tid & 255;
        const int q = o >> 5, kk = o & 31;
        float s0 = 0.f, s1 = 0.f, s2 = 0.f, s3 = 0.f;
#pragma unroll
        for (int b = 0; b < GAA / 2; b += 4) {     // 32 loads, 4 accumulators
            s0 += g_pmom[j * (GAA / 2) + b + 0][q][kk];
            s1 += g_pmom[j * (GAA / 2) + b + 1][q][kk];
            s2 += g_pmom[j * (GAA / 2) + b + 2][q][kk];
            s3 += g_pmom[j * (GAA / 2) + b + 3][q][kk];
        }
        sred[j][q][kk] = (s0 + s1) + (s2 + s3);
    }
    if (tid < 8 * MM) {                            // max partials (8 strided each)
        const int i = tid >> 5;
        float v = -1e30f;
#pragma unroll
        for (int jj = 0; jj < GAA / 8; ++jj) v = fmaxf(v, g_pmax[i + jj * 8][lane]);
        smax2[i][lane] = v;
    }
    __syncthreads();
    if (tid < 32) {
        float v = smax2[0][tid];
#pragma unroll
        for (int i = 1; i < 8; ++i) v = fmaxf(v, smax2[i][tid]);
        float scale = 1.0f / (2.0f * sigma[0] * sqrtf(2.0f));
        float f = scale * __expf(-v);
        sf[tid] = f;
        g_f[tid] = f;
    }
    __syncthreads();
    if (tid < NMOM * MM) {
        const int q = tid >> 5, kk = tid & 31;
        float s = sred[0][q][kk] + sred[1][q][kk];
        float f = sf[kk], fp = 1.0f;
#pragma unroll
        for (int i = 0; i < NMOM - 1; ++i) if (i < q) fp *= f;
        sM[q][kk] = s * fp;                        // Mn_q = M'_q * f^q
    }
    __syncthreads();
    if (tid < NMOM * MM) {                         // b_m = sum_p A[m][p] * Mn_p
        const int md = tid >> 5, kk = tid & 31;
        float bm = 0.0f;
#pragma unroll
        for (int p = 0; p < NMOM; ++p) bm = fmaf(d_A[md][p], sM[p][kk], bm);
        g_bco[md][kk] = bm;
        if (md == 0) g_bco[NMOM][kk] = sM[0][kk];  // W
    }
}

// ---------------------------------------------------------------------------
// kB: pure eval, no election. Writes one partial per block.
// ---------------------------------------------------------------------------
__global__ void __launch_bounds__(TBB, 1) kB(const float* __restrict__ risk,
                                             const float* __restrict__ expr,
                                             const float* __restrict__ tr,
                                             const float* __restrict__ ev) {
    const int tid  = threadIdx.x;
    const int warp = tid >> 5, lane = tid & 31;

    __shared__ float wred[NWBB];

    // issue all loads up front (element data + broadcast coefficients)
    const int idx   = blockIdx.x * TBB + tid;      // lane = column
    const float rv  = risk[idx];
    const float dd  = expr[idx] - tr[idx];
    const float evv = ev[idx];

    float bb[NMOM];
#pragma unroll
    for (int q = 0; q < NMOM; ++q) bb[q] = g_bco[q][lane];
    const float W = g_bco[NMOM][lane];
    const float f = g_f[lane];

    const float T = __expf(dd);
    const float w = __expf(rv);

    float x = T * f;
    float s = bb[NMOM - 1];
#pragma unroll
    for (int q = NMOM - 2; q >= 0; --q) s = fmaf(s, x, bb[q]);
    float cum = fmaf(0.5f, W + w, -s);
    float acc = (rv - __logf(cum)) * evv;

#pragma unroll
    for (int o = 16; o > 0; o >>= 1) acc += __shfl_down_sync(0xffffffffu, acc, o);
    if (lane == 0) wred[warp] = acc;
    __syncthreads();
    if (tid == 0) {
        float b0 = 0.f, b1 = 0.f, b2 = 0.f, b3 = 0.f;
#pragma unroll
        for (int i = 0; i < NWBB; i += 4) {
            b0 += wred[i]; b1 += wred[i + 1]; b2 += wred[i + 2]; b3 += wred[i + 3];
        }
        g_part[blockIdx.x] = (b0 + b1) + (b2 + b3);
    }
}

// ---------------------------------------------------------------------------
// kD: one warp — deterministic final reduce of 128 partials -> -loss.
// ---------------------------------------------------------------------------
__global__ void __launch_bounds__(32) kD(float* __restrict__ out) {
    const int lane = threadIdx.x;
    float v0 = g_part[lane],      v1 = g_part[lane + 32];
    float v2 = g_part[lane + 64], v3 = g_part[lane + 96];
    float v = (v0 + v1) + (v2 + v3);
#pragma unroll
    for (int o = 16; o > 0; o >>= 1) v += __shfl_down_sync(0xffffffffu, v, o);
    if (lane == 0) out[0] = -v;
}

extern "C" void kernel_launch(void* const* d_in, const int* in_sizes, int n_in,
                              void* d_out, int out_size) {
    const float* risk  = (const float*)d_in[0];
    const float* expr  = (const float*)d_in[1];
    const float* tr    = (const float*)d_in[2];
    const float* ev    = (const float*)d_in[3];
    const float* sigma = (const float*)d_in[4];
    float* out = (float*)d_out;

    kA<<<GAA, TBA>>>(risk, expr, tr);
    kC<<<1, 512>>>(sigma);
    kB<<<GBB, TBB>>>(risk, expr, tr, ev);
    kD<<<1, 32>>>(out);
}

// round 13
// speedup vs baseline: 1.1875x; 1.1875x over previous
#include <cuda_runtime.h>
#include <cooperative_groups.h>
#include <math.h>

namespace cg = cooperative_groups;

#define NN 2048
#define MM 32
#define NMOM 8                 // moments M_0..M_7 (degree-7 erf series)
#define CLU 8                  // cluster size = whole grid
#define TB 1024                // threads per CTA (32 warps)
#define NW 32
#define EPT 8                  // elements per thread: 65536 / (8*1024)

// A[m][p] = C[(m+p-1)/2] * binom(m+p, m) * (-1)^p for (m+p) odd <= 7, else 0.
// 0.5*erf(d) ~ C0 d + C1 d^3 + C2 d^5 + C3 d^7  (|d| <= 0.3536, trunc ~5e-7 rel)
__device__ __constant__ float d_A[NMOM][NMOM] = {
  {0.f,-0.5641895835477563f,0.f, 0.18806319451591878f,0.f,-0.05641895835477563f,0.f, 0.013433085322565627f},
  {0.5641895835477563f,0.f,-0.5641895835477563f,0.f, 0.28209479177387815f,0.f,-0.09403159725795939f,0.f},
  {0.f, 0.5641895835477563f,0.f,-0.5641895835477563f,0.f, 0.28209479177387817f,0.f,0.f},
  {-0.18806319451591878f,0.f, 0.5641895835477563f,0.f,-0.47015798628979696f,0.f,0.f,0.f},
  {0.f,-0.28209479177387815f,0.f, 0.47015798628979696f,0.f,0.f,0.f,0.f},
  {0.05641895835477563f,0.f,-0.28209479177387817f,0.f,0.f,0.f,0.f,0.f},
  {0.f, 0.09403159725795939f,0.f,0.f,0.f,0.f,0.f,0.f},
  {-0.013433085322565627f,0.f,0.f,0.f,0.f,0.f,0.f,0.f}
};

__global__ void __launch_bounds__(TB, 1) __cluster_dims__(CLU, 1, 1)
fused(const float* __restrict__ risk,
      const float* __restrict__ expr,
      const float* __restrict__ tr,
      const float* __restrict__ ev,
      const float* __restrict__ sigma,
      float* __restrict__ out) {
    cg::cluster_group cluster = cg::this_cluster();
    const int tid  = threadIdx.x;
    const int warp = tid >> 5, lane = tid & 31;

    // published (read by peer CTAs via DSMEM) — do not overwrite after publish
    __shared__ float pub_mom[NMOM][MM];   // this CTA's raw moment partials
    __shared__ float pub_max[MM];         // this CTA's per-column max(diff)
    __shared__ float pub_loss;            // this CTA's loss partial
    // private working storage
    __shared__ float smom[NW][NMOM][MM];  // 32 KB
    __shared__ float smax[NW][MM];        // 4 KB
    __shared__ float sM[NMOM][MM];        // cluster-wide raw moments
    __shared__ float sfp[NMOM][MM];       // f^q per column
    __shared__ float sbb[NMOM + 1][MM];   // b_0..b_7, row NMOM = W
    __shared__ float wred[NW];

    const float sigv = sigma[0];
    const int   base = blockIdx.x * (TB * EPT) + tid;   // lane = column (stride 1024)

    // ---------------- Phase 1: moments + max over 8 elements/thread ----------------
    float rv[EPT], T[EPT], evv[EPT];
    float mx = -1e30f;
    float m[NMOM];
#pragma unroll
    for (int q = 0; q < NMOM; ++q) m[q] = 0.0f;

#pragma unroll
    for (int e = 0; e < EPT; ++e) {
        const int idx = base + e * TB;
        rv[e]  = risk[idx];
        float d = expr[idx] - tr[idx];
        evv[e] = ev[idx];
        T[e]   = __expf(d);
        float w = __expf(rv[e]);
        mx = fmaxf(mx, d);
        float p = w;
        m[0] += p;
#pragma unroll
        for (int q = 1; q < NMOM; ++q) { p *= T[e]; m[q] += p; }
    }
    smax[warp][lane] = mx;
#pragma unroll
    for (int q = 0; q < NMOM; ++q) smom[warp][q][lane] = m[q];
    __syncthreads();

    if (tid < 32) {                        // column max over 32 warps
        float v = smax[0][tid];
#pragma unroll
        for (int i = 1; i < NW; ++i) v = fmaxf(v, smax[i][tid]);
        pub_max[tid] = v;
    }
    if (tid < NMOM * MM) {                 // moment sums over 32 warps (4-acc)
        const int q = tid >> 5, kk = tid & 31;
        float s0 = 0.f, s1 = 0.f, s2 = 0.f, s3 = 0.f;
#pragma unroll
        for (int i = 0; i < NW; i += 4) {
            s0 += smom[i + 0][q][kk];
            s1 += smom[i + 1][q][kk];
            s2 += smom[i + 2][q][kk];
            s3 += smom[i + 3][q][kk];
        }
        pub_mom[q][kk] = (s0 + s1) + (s2 + s3);
    }

    // ---------------- Cluster barrier #1 (partials published) ----------------
    cluster.sync();

    // ---------------- Phase 2: redundant coefficient build (DSMEM reads) ------
    if (tid < NMOM * MM) {                 // sum this (q,k) over all 8 CTAs
        const int q = tid >> 5, kk = tid & 31;
        float s0 = 0.f, s1 = 0.f;
#pragma unroll
        for (int r = 0; r < CLU; r += 2) {
            const float* p0 = cluster.map_shared_rank(&pub_mom[q][kk], r);
            const float* p1 = cluster.map_shared_rank(&pub_mom[q][kk], r + 1);
            s0 += *p0; s1 += *p1;
        }
        sM[q][kk] = s0 + s1;
    }
    if (tid < 32) {                        // cluster max -> f and its powers
        float v = -1e30f;
#pragma unroll
        for (int r = 0; r < CLU; ++r) {
            const float* p = cluster.map_shared_rank(&pub_max[tid], r);
            v = fmaxf(v, *p);
        }
        float scale = 1.0f / (2.0f * sigv * sqrtf(2.0f));
        float f = scale * __expf(-v);
        float fp = 1.0f;
#pragma unroll
        for (int q = 0; q < NMOM; ++q) { sfp[q][tid] = fp; fp *= f; }
    }
    __syncthreads();
    if (tid < NMOM * MM) {                 // b_m = sum_p A[m][p] * M'_p * f^p
        const int md = tid >> 5, kk = tid & 31;
        float bm = 0.0f;
#pragma unroll
        for (int p = 0; p < NMOM; ++p) bm = fmaf(d_A[md][p], sM[p][kk] * sfp[p][kk], bm);
        sbb[md][kk] = bm;
        if (md == 0) sbb[NMOM][kk] = sM[0][kk];   // W
    }
    __syncthreads();

    // ---------------- Phase 3: eval (rv, T, evv still live) ----------------
    float bb[NMOM];
#pragma unroll
    for (int q = 0; q < NMOM; ++q) bb[q] = sbb[q][lane];
    const float W = sbb[NMOM][lane];
    const float f = sfp[1][lane];          // f^1

    float acc = 0.0f;
#pragma unroll
    for (int e = 0; e < EPT; ++e) {
        float w = __expf(rv[e]);
        float x = T[e] * f;
        float s = bb[NMOM - 1];
#pragma unroll
        for (int q = NMOM - 2; q >= 0; --q) s = fmaf(s, x, bb[q]);
        float cum = fmaf(0.5f, W + w, -s);
        acc += (rv[e] - __logf(cum)) * evv[e];
    }
#pragma unroll
    for (int o = 16; o > 0; o >>= 1) acc += __shfl_down_sync(0xffffffffu, acc, o);
    if (lane == 0) wred[warp] = acc;
    __syncthreads();
    if (tid == 0) {
        float b0 = 0.f, b1 = 0.f, b2 = 0.f, b3 = 0.f;
#pragma unroll
        for (int i = 0; i < NW; i += 4) {
            b0 += wred[i]; b1 += wred[i + 1]; b2 += wred[i + 2]; b3 += wred[i + 3];
        }
        pub_loss = (b0 + b1) + (b2 + b3);
    }

    // ---------------- Cluster barrier #2 (loss partials published) ----------------
    cluster.sync();

    if (blockIdx.x == 0 && warp == 0 && lane < CLU) {
        const float* p = cluster.map_shared_rank(&pub_loss, lane);
        float v = *p;
#pragma unroll
        for (int o = CLU / 2; o > 0; o >>= 1)
            v += __shfl_down_sync(0x000000ffu, v, o);
        if (lane == 0) out[0] = -v;
    }

    // ---------------- Cluster barrier #3: no CTA may exit while CTA 0 is
    // still reading peer DSMEM above (exit would invalidate its SMEM). -------
    cluster.sync();
}

extern "C" void kernel_launch(void* const* d_in, const int* in_sizes, int n_in,
                              void* d_out, int out_size) {
    const float* risk  = (const float*)d_in[0];
    const float* expr  = (const float*)d_in[1];
    const float* tr    = (const float*)d_in[2];
    const float* ev    = (const float*)d_in[3];
    const float* sigma = (const float*)d_in[4];
    float* out = (float*)d_out;

    fused<<<CLU, TB>>>(risk, expr, tr, ev, sigma, out);
}

// round 14
// speedup vs baseline: 1.4669x; 1.2353x over previous
#include <cuda_runtime.h>
#include <cooperative_groups.h>
#include <math.h>

namespace cg = cooperative_groups;

#define NN 2048
#define MM 32
#define NMOM 8                 // moments M_0..M_7 (degree-7 erf series)
#define TB 1024                // threads per CTA (32 warps)
#define NW 32

// A[m][p] = C[(m+p-1)/2] * binom(m+p, m) * (-1)^p for (m+p) odd <= 7, else 0.
// 0.5*erf(d) ~ C0 d + C1 d^3 + C2 d^5 + C3 d^7  (|d| <= 0.3536, trunc ~5e-7 rel)
__device__ __constant__ float d_A[NMOM][NMOM] = {
  {0.f,-0.5641895835477563f,0.f, 0.18806319451591878f,0.f,-0.05641895835477563f,0.f, 0.013433085322565627f},
  {0.5641895835477563f,0.f,-0.5641895835477563f,0.f, 0.28209479177387815f,0.f,-0.09403159725795939f,0.f},
  {0.f, 0.5641895835477563f,0.f,-0.5641895835477563f,0.f, 0.28209479177387817f,0.f,0.f},
  {-0.18806319451591878f,0.f, 0.5641895835477563f,0.f,-0.47015798628979696f,0.f,0.f,0.f},
  {0.f,-0.28209479177387815f,0.f, 0.47015798628979696f,0.f,0.f,0.f,0.f},
  {0.05641895835477563f,0.f,-0.28209479177387817f,0.f,0.f,0.f,0.f,0.f},
  {0.f, 0.09403159725795939f,0.f,0.f,0.f,0.f,0.f,0.f},
  {-0.013433085322565627f,0.f,0.f,0.f,0.f,0.f,0.f,0.f}
};

template <int CLUS>
__global__ void __launch_bounds__(TB, 1)
fused(const float* __restrict__ risk,
      const float* __restrict__ expr,
      const float* __restrict__ tr,
      const float* __restrict__ ev,
      const float* __restrict__ sigma,
      float* __restrict__ out) {
    constexpr int EPT = (NN * MM) / (CLUS * TB);   // 8 @ CLUS=8, 4 @ CLUS=16
    cg::cluster_group cluster = cg::this_cluster();
    const int tid  = threadIdx.x;
    const int warp = tid >> 5, lane = tid & 31;

    // published (read by peer CTAs via DSMEM) — do not overwrite after publish
    __shared__ float pub_mom[NMOM][MM];   // this CTA's raw moment partials
    __shared__ float pub_max[MM];         // this CTA's per-column max(diff)
    __shared__ float pub_loss;            // this CTA's loss partial
    // private working storage
    __shared__ float smom[NW][NMOM][MM];  // 32 KB
    __shared__ float smax[NW][MM];        // 4 KB
    __shared__ float sM[NMOM][MM];        // cluster-wide raw moments
    __shared__ float sfp[NMOM][MM];       // f^q per column
    __shared__ float sbb[NMOM + 1][MM];   // b_0..b_7, row NMOM = W
    __shared__ float wred[NW];

    const float sigv = sigma[0];
    const int   base = blockIdx.x * (TB * EPT) + tid;   // lane = column (stride 1024)

    // ---------------- Phase 1: moments + max over EPT elements/thread --------------
    float rv[EPT], T[EPT], evv[EPT];
    float mx = -1e30f;
    float m[NMOM];
#pragma unroll
    for (int q = 0; q < NMOM; ++q) m[q] = 0.0f;

#pragma unroll
    for (int e = 0; e < EPT; ++e) {
        const int idx = base + e * TB;
        rv[e]  = risk[idx];
        float d = expr[idx] - tr[idx];
        evv[e] = ev[idx];
        T[e]   = __expf(d);
        float w = __expf(rv[e]);
        mx = fmaxf(mx, d);
        float p = w;
        m[0] += p;
#pragma unroll
        for (int q = 1; q < NMOM; ++q) { p *= T[e]; m[q] += p; }
    }
    smax[warp][lane] = mx;
#pragma unroll
    for (int q = 0; q < NMOM; ++q) smom[warp][q][lane] = m[q];
    __syncthreads();

    if (tid < 32) {                        // column max over 32 warps
        float v = smax[0][tid];
#pragma unroll
        for (int i = 1; i < NW; ++i) v = fmaxf(v, smax[i][tid]);
        pub_max[tid] = v;
    }
    if (tid < NMOM * MM) {                 // moment sums over 32 warps (4-acc)
        const int q = tid >> 5, kk = tid & 31;
        float s0 = 0.f, s1 = 0.f, s2 = 0.f, s3 = 0.f;
#pragma unroll
        for (int i = 0; i < NW; i += 4) {
            s0 += smom[i + 0][q][kk];
            s1 += smom[i + 1][q][kk];
            s2 += smom[i + 2][q][kk];
            s3 += smom[i + 3][q][kk];
        }
        pub_mom[q][kk] = (s0 + s1) + (s2 + s3);
    }

    // ---------------- Cluster barrier #1 (partials published) ----------------
    cluster.sync();

    // ---------------- Phase 2: redundant coefficient build (DSMEM reads) ------
    if (tid < NMOM * MM) {                 // sum this (q,k) over all CLUS CTAs
        const int q = tid >> 5, kk = tid & 31;
        float s0 = 0.f, s1 = 0.f;
#pragma unroll
        for (int r = 0; r < CLUS; r += 2) {
            const float* p0 = cluster.map_shared_rank(&pub_mom[q][kk], r);
            const float* p1 = cluster.map_shared_rank(&pub_mom[q][kk], r + 1);
            s0 += *p0; s1 += *p1;
        }
        sM[q][kk] = s0 + s1;
    }
    if (tid < 32) {                        // cluster max -> f and its powers
        float v = -1e30f;
#pragma unroll
        for (int r = 0; r < CLUS; ++r) {
            const float* p = cluster.map_shared_rank(&pub_max[tid], r);
            v = fmaxf(v, *p);
        }
        float scale = 1.0f / (2.0f * sigv * sqrtf(2.0f));
        float f = scale * __expf(-v);
        float fp = 1.0f;
#pragma unroll
        for (int q = 0; q < NMOM; ++q) { sfp[q][tid] = fp; fp *= f; }
    }
    __syncthreads();
    if (tid < NMOM * MM) {                 // b_m = sum_p A[m][p] * M'_p * f^p
        const int md = tid >> 5, kk = tid & 31;
        float bm = 0.0f;
#pragma unroll
        for (int p = 0; p < NMOM; ++p) bm = fmaf(d_A[md][p], sM[p][kk] * sfp[p][kk], bm);
        sbb[md][kk] = bm;
        if (md == 0) sbb[NMOM][kk] = sM[0][kk];   // W
    }
    __syncthreads();

    // ---------------- Phase 3: eval (rv, T, evv still live) ----------------
    float bb[NMOM];
#pragma unroll
    for (int q = 0; q < NMOM; ++q) bb[q] = sbb[q][lane];
    const float W = sbb[NMOM][lane];
    const float f = sfp[1][lane];          // f^1

    float acc = 0.0f;
#pragma unroll
    for (int e = 0; e < EPT; ++e) {
        float w = __expf(rv[e]);
        float x = T[e] * f;
        float s = bb[NMOM - 1];
#pragma unroll
        for (int q = NMOM - 2; q >= 0; --q) s = fmaf(s, x, bb[q]);
        float cum = fmaf(0.5f, W + w, -s);
        acc += (rv[e] - __logf(cum)) * evv[e];
    }
#pragma unroll
    for (int o = 16; o > 0; o >>= 1) acc += __shfl_down_sync(0xffffffffu, acc, o);
    if (lane == 0) wred[warp] = acc;
    __syncthreads();
    if (tid == 0) {
        float b0 = 0.f, b1 = 0.f, b2 = 0.f, b3 = 0.f;
#pragma unroll
        for (int i = 0; i < NW; i += 4) {
            b0 += wred[i]; b1 += wred[i + 1]; b2 += wred[i + 2]; b3 += wred[i + 3];
        }
        pub_loss = (b0 + b1) + (b2 + b3);
    }

    // ---------------- Cluster barrier #2 (loss partials published) ----------------
    cluster.sync();

    if (blockIdx.x == 0 && warp == 0 && lane < CLUS) {
        const float* p = cluster.map_shared_rank(&pub_loss, lane);
        float v = *p;
#pragma unroll
        for (int o = CLUS / 2; o > 0; o >>= 1)
            v += __shfl_down_sync((unsigned)((1ull << CLUS) - 1), v, o);
        if (lane == 0) out[0] = -v;
    }

    // ---------------- Cluster barrier #3: no CTA exits while CTA 0 reads peers ----
    cluster.sync();
}

extern "C" void kernel_launch(void* const* d_in, const int* in_sizes, int n_in,
                              void* d_out, int out_size) {
    const float* risk  = (const float*)d_in[0];
    const float* expr  = (const float*)d_in[1];
    const float* tr    = (const float*)d_in[2];
    const float* ev    = (const float*)d_in[3];
    const float* sigma = (const float*)d_in[4];
    float* out = (float*)d_out;

    // Host-side setup: runs at capture time only (graph replays skip this).
    // Deterministic: same device -> same decision on every call.
    int use16 = 0;
    if (cudaFuncSetAttribute((const void*)fused<16>,
                             cudaFuncAttributeNonPortableClusterSizeAllowed, 1)
        == cudaSuccess) {
        cudaLaunchConfig_t probe = {};
        probe.gridDim  = {16, 1, 1};
        probe.blockDim = {TB, 1, 1};
        int maxC = 0;
        if (cudaOccupancyMaxPotentialClusterSize(&maxC, (const void*)fused<16>, &probe)
            == cudaSuccess && maxC >= 16)
            use16 = 1;
    }

    cudaLaunchAttribute attrs[1];
    attrs[0].id = cudaLaunchAttributeClusterDimension;
    cudaLaunchConfig_t cfg = {};
    cfg.blockDim = {TB, 1, 1};
    cfg.attrs    = attrs;
    cfg.numAttrs = 1;

    if (use16) {
        cfg.gridDim = {16, 1, 1};
        attrs[0].val.clusterDim = {16, 1, 1};
        cudaLaunchKernelEx(&cfg, fused<16>, risk, expr, tr, ev, sigma, out);
    } else {
        cfg.gridDim = {8, 1, 1};
        attrs[0].val.clusterDim = {8, 1, 1};
        cudaLaunchKernelEx(&cfg, fused<8>, risk, expr, tr, ev, sigma, out);
    }
}